// round 3
// baseline (speedup 1.0000x reference)
#include <cuda_runtime.h>

// RNN_33964601377372: h_{t+1} = relu(x_t*W_ih + b_ih + b_hh + W_hh h_t), out = fc(h_T)
//
// 8 lanes per batch = 4 row-groups (5 rows each) x 2 j-halves (10 terms each).
// Lane (q, half): rows q*5..q*5+4, recurrence terms j in [half*10, half*10+10).
// Rows packed as two f32x2 chains + one scalar chain. After the partial dot
// products, one xor-4 butterfly combines the two j-halves; both halves keep a
// copy of h so next-step broadcasts are width-8 idx shuffles.
// Block = 224 threads (28 batches) -> 147 CTAs = single wave, ~1.75 warps/SMSP.

#define HID 20
#define GRP 8   // lanes per batch

typedef unsigned long long u64;

__device__ __forceinline__ u64 pack2(float lo, float hi) {
    u64 r; asm("mov.b64 %0, {%1, %2};" : "=l"(r) : "f"(lo), "f"(hi)); return r;
}
__device__ __forceinline__ u64 dup2(float v) {
    u64 r; asm("mov.b64 %0, {%1, %1};" : "=l"(r) : "f"(v)); return r;
}
__device__ __forceinline__ void unpack2(u64 p, float& lo, float& hi) {
    asm("mov.b64 {%0, %1}, %2;" : "=f"(lo), "=f"(hi) : "l"(p));
}
__device__ __forceinline__ u64 ffma2(u64 a, u64 b, u64 c) {
    u64 d; asm("fma.rn.f32x2 %0, %1, %2, %3;" : "=l"(d) : "l"(a), "l"(b), "l"(c)); return d;
}
__device__ __forceinline__ u64 fadd2(u64 a, u64 b) {
    u64 d; asm("add.rn.f32x2 %0, %1, %2;" : "=l"(d) : "l"(a), "l"(b)); return d;
}

__global__ __launch_bounds__(224) void rnn_fused_kernel(
    const float* __restrict__ x,    // [B, T]
    const float* __restrict__ Wih,  // [H]
    const float* __restrict__ Whh,  // [H, H] row-major
    const float* __restrict__ bih,  // [H]
    const float* __restrict__ bhh,  // [H]
    const float* __restrict__ fcw,  // [H]
    const float* __restrict__ fcb,  // [1]
    float* __restrict__ out,        // [B]
    int B, int T)
{
    const int tid = blockIdx.x * blockDim.x + threadIdx.x;
    int batch = tid >> 3;
    const int e    = tid & 7;    // lane within batch group
    const int q    = e & 3;      // row group: rows q*5 .. q*5+4
    const int half = e >> 2;     // j half: terms half*10 .. half*10+9
    const bool real = (batch < B);
    if (batch >= B) batch = B - 1;   // clamp (keep shuffle lanes active)

    const int r0 = q * 5;
    const int j0 = half * 10;

    // Weight slices: rows (r0,r0+1)->A, (r0+2,r0+3)->B, r0+4->C over my 10 j's.
    u64 wA[10], wB[10];
    float wC[10];
#pragma unroll
    for (int jj = 0; jj < 10; ++jj) {
        int J = j0 + jj;
        wA[jj] = pack2(Whh[(r0 + 0) * HID + J], Whh[(r0 + 1) * HID + J]);
        wB[jj] = pack2(Whh[(r0 + 2) * HID + J], Whh[(r0 + 3) * HID + J]);
        wC[jj] = Whh[(r0 + 4) * HID + J];
    }

    // Only half 0 injects x-projection + bias; half 1 starts from zero.
    u64 wihA = 0, wihB = 0, biasA = 0, biasB = 0;
    float wihC = 0.0f, biasC = 0.0f;
    if (half == 0) {
        wihA  = pack2(Wih[r0 + 0], Wih[r0 + 1]);
        wihB  = pack2(Wih[r0 + 2], Wih[r0 + 3]);
        wihC  = Wih[r0 + 4];
        biasA = pack2(bih[r0 + 0] + bhh[r0 + 0], bih[r0 + 1] + bhh[r0 + 1]);
        biasB = pack2(bih[r0 + 2] + bhh[r0 + 2], bih[r0 + 3] + bhh[r0 + 3]);
        biasC = bih[r0 + 4] + bhh[r0 + 4];
    }

    // Shuffle sources (within width-8 segment) for my two j row-groups.
    const int src0 = 6 * half;      // rows j0..j0+4 live in lane (2*half)+4*half
    const int src1 = 6 * half + 1;  // rows j0+5..j0+9

    float h[5];
#pragma unroll
    for (int r = 0; r < 5; ++r) h[r] = 0.0f;

    const float* xb = x + (size_t)batch * T;   // 4000B stride, 16B-aligned
    const float4* xb4 = (const float4*)xb;
    const int nChunks = T >> 2;

    float4 xv = (nChunks > 0) ? xb4[0] : make_float4(0.f, 0.f, 0.f, 0.f);
    float4 xnext = xv;

    for (int c = 0; c < nChunks; ++c) {
        if (c + 1 < nChunks) xnext = xb4[c + 1];
#pragma unroll
        for (int s = 0; s < 4; ++s) {
            float xt = (s == 0) ? xv.x : (s == 1) ? xv.y : (s == 2) ? xv.z : xv.w;
            u64 xt2 = dup2(xt);
            u64 accA = ffma2(xt2, wihA, biasA);
            u64 accB = ffma2(xt2, wihB, biasB);
            float accC = fmaf(xt, wihC, biasC);
#pragma unroll
            for (int jj = 0; jj < 10; ++jj) {
                float hj = __shfl_sync(0xffffffffu, h[jj % 5], (jj < 5) ? src0 : src1, GRP);
                u64 hj2 = dup2(hj);
                accA = ffma2(hj2, wA[jj], accA);
                accB = ffma2(hj2, wB[jj], accB);
                accC = fmaf(hj, wC[jj], accC);
            }
            // Combine the two j-halves: xor-4 butterfly within the 8-lane group.
            {
                float alo, ahi, blo, bhi;
                unpack2(accA, alo, ahi);
                unpack2(accB, blo, bhi);
                float palo = __shfl_xor_sync(0xffffffffu, alo, 4, GRP);
                float pahi = __shfl_xor_sync(0xffffffffu, ahi, 4, GRP);
                float pblo = __shfl_xor_sync(0xffffffffu, blo, 4, GRP);
                float pbhi = __shfl_xor_sync(0xffffffffu, bhi, 4, GRP);
                float pc   = __shfl_xor_sync(0xffffffffu, accC, 4, GRP);
                accA = fadd2(accA, pack2(palo, pahi));
                accB = fadd2(accB, pack2(pblo, pbhi));
                accC += pc;
            }
            float a0, a1, a2, a3;
            unpack2(accA, a0, a1);
            unpack2(accB, a2, a3);
            h[0] = fmaxf(a0, 0.0f);
            h[1] = fmaxf(a1, 0.0f);
            h[2] = fmaxf(a2, 0.0f);
            h[3] = fmaxf(a3, 0.0f);
            h[4] = fmaxf(accC, 0.0f);
        }
        xv = xnext;
    }

    // Scalar tail (not taken for T=1000).
    for (int t = nChunks << 2; t < T; ++t) {
        float xt = xb[t];
        u64 xt2 = dup2(xt);
        u64 accA = ffma2(xt2, wihA, biasA);
        u64 accB = ffma2(xt2, wihB, biasB);
        float accC = fmaf(xt, wihC, biasC);
#pragma unroll
        for (int jj = 0; jj < 10; ++jj) {
            float hj = __shfl_sync(0xffffffffu, h[jj % 5], (jj < 5) ? src0 : src1, GRP);
            u64 hj2 = dup2(hj);
            accA = ffma2(hj2, wA[jj], accA);
            accB = ffma2(hj2, wB[jj], accB);
            accC = fmaf(hj, wC[jj], accC);
        }
        {
            float alo, ahi, blo, bhi;
            unpack2(accA, alo, ahi);
            unpack2(accB, blo, bhi);
            float palo = __shfl_xor_sync(0xffffffffu, alo, 4, GRP);
            float pahi = __shfl_xor_sync(0xffffffffu, ahi, 4, GRP);
            float pblo = __shfl_xor_sync(0xffffffffu, blo, 4, GRP);
            float pbhi = __shfl_xor_sync(0xffffffffu, bhi, 4, GRP);
            float pc   = __shfl_xor_sync(0xffffffffu, accC, 4, GRP);
            accA = fadd2(accA, pack2(palo, pahi));
            accB = fadd2(accB, pack2(pblo, pbhi));
            accC += pc;
        }
        float a0, a1, a2, a3;
        unpack2(accA, a0, a1);
        unpack2(accB, a2, a3);
        h[0] = fmaxf(a0, 0.0f);
        h[1] = fmaxf(a1, 0.0f);
        h[2] = fmaxf(a2, 0.0f);
        h[3] = fmaxf(a3, 0.0f);
        h[4] = fmaxf(accC, 0.0f);
    }

    // Head: out[b] = h . fc_w + fc_b. Reduce across the 4 row-groups (both
    // halves hold identical h; lanes 0..3 form a complete set).
    float p = 0.0f;
#pragma unroll
    for (int r = 0; r < 5; ++r) p = fmaf(h[r], fcw[r0 + r], p);
    p += __shfl_xor_sync(0xffffffffu, p, 1, GRP);
    p += __shfl_xor_sync(0xffffffffu, p, 2, GRP);
    if (e == 0 && real) out[batch] = p + fcb[0];
}

extern "C" void kernel_launch(void* const* d_in, const int* in_sizes, int n_in,
                              void* d_out, int out_size)
{
    const float* x    = (const float*)d_in[0];
    const float* Wih  = (const float*)d_in[1];
    const float* Whh  = (const float*)d_in[2];
    const float* bih  = (const float*)d_in[3];
    const float* bhh  = (const float*)d_in[4];
    const float* fcw  = (const float*)d_in[5];
    const float* fcb  = (const float*)d_in[6];
    float* out = (float*)d_out;

    int B = out_size;
    int T = in_sizes[0] / B;

    const int threads = 224;                   // 28 batches per CTA, 7 warps
    int total = B * GRP;                       // 32768 lanes
    int blocks = (total + threads - 1) / threads;  // 147 CTAs at B=4096
    rnn_fused_kernel<<<blocks, threads>>>(x, Wih, Whh, bih, bhh, fcw, fcb, out, B, T);
}

// round 4
// speedup vs baseline: 1.1320x; 1.1320x over previous
#include <cuda_runtime.h>

// RNN_33964601377372: h_{t+1} = relu(x_t*W_ih + b_ih + b_hh + W_hh h_t), out = fc(h_T)
//
// Quad layout (4 lanes/batch, 5 rows/lane), j-packed f32x2 math:
// shuffle 20 h scalars, pack into 10 (h_{2k}, h_{2k+1}) pairs, and run each of
// the 5 local rows as one j-packed FFMA2 chain (10 deep). Per step per lane:
// 20 SHFL + 10 pack + 1 dup (ALU) + 55 FFMA2 + 5 FADD (fma pipe) + 5 FMNMX (alu).
// fma-pipe ops = 60 -> single-warp rt floor = 120 cyc/step.

#define HID 20
#define QUAD 4

typedef unsigned long long u64;

__device__ __forceinline__ u64 pack2(float lo, float hi) {
    u64 r; asm("mov.b64 %0, {%1, %2};" : "=l"(r) : "f"(lo), "f"(hi)); return r;
}
__device__ __forceinline__ u64 dup2(float v) {
    u64 r; asm("mov.b64 %0, {%1, %1};" : "=l"(r) : "f"(v)); return r;
}
__device__ __forceinline__ void unpack2(u64 p, float& lo, float& hi) {
    asm("mov.b64 {%0, %1}, %2;" : "=f"(lo), "=f"(hi) : "l"(p));
}
__device__ __forceinline__ u64 ffma2(u64 a, u64 b, u64 c) {
    u64 d; asm("fma.rn.f32x2 %0, %1, %2, %3;" : "=l"(d) : "l"(a), "l"(b), "l"(c)); return d;
}

__global__ __launch_bounds__(64) void rnn_fused_kernel(
    const float* __restrict__ x,    // [B, T]
    const float* __restrict__ Wih,  // [H]
    const float* __restrict__ Whh,  // [H, H] row-major
    const float* __restrict__ bih,  // [H]
    const float* __restrict__ bhh,  // [H]
    const float* __restrict__ fcw,  // [H]
    const float* __restrict__ fcb,  // [1]
    float* __restrict__ out,        // [B]
    int B, int T)
{
    int tid = blockIdx.x * blockDim.x + threadIdx.x;
    int batch = tid >> 2;
    int q = tid & 3;           // lane within quad: owns rows q*5 .. q*5+4
    if (batch >= B) return;
    const int r0 = q * 5;

    // j-packed weights: wJ[r][k] = (Whh[r0+r][2k], Whh[r0+r][2k+1])
    u64 wJ[5][10];
#pragma unroll
    for (int r = 0; r < 5; ++r)
#pragma unroll
        for (int k = 0; k < 10; ++k)
            wJ[r][k] = pack2(Whh[(r0 + r) * HID + 2 * k],
                             Whh[(r0 + r) * HID + 2 * k + 1]);

    // x-projection packed into lo lane only: acc = ffma2(xt2, (wih,0), (bias,0))
    u64 wihP[5], biasP[5];
#pragma unroll
    for (int r = 0; r < 5; ++r) {
        wihP[r]  = pack2(Wih[r0 + r], 0.0f);
        biasP[r] = pack2(bih[r0 + r] + bhh[r0 + r], 0.0f);
    }

    float h[5];
#pragma unroll
    for (int r = 0; r < 5; ++r) h[r] = 0.0f;

    const float* xb = x + (size_t)batch * T;   // 4000B stride, 16B-aligned
    const float4* xb4 = (const float4*)xb;
    const int nChunks = T >> 2;

    float4 xv = (nChunks > 0) ? xb4[0] : make_float4(0.f, 0.f, 0.f, 0.f);
    float4 xnext = xv;

    for (int c = 0; c < nChunks; ++c) {
        if (c + 1 < nChunks) xnext = xb4[c + 1];  // 4 steps of load hiding
#pragma unroll
        for (int s = 0; s < 4; ++s) {
            float xt = (s == 0) ? xv.x : (s == 1) ? xv.y : (s == 2) ? xv.z : xv.w;

            // Broadcast all 20 h values within the quad (issued first so the
            // x-proj FFMA2s below fill the shuffle-latency window).
            float hj[HID];
#pragma unroll
            for (int j = 0; j < HID; ++j)
                hj[j] = __shfl_sync(0xffffffffu, h[j % 5], j / 5, QUAD);

            u64 xt2 = dup2(xt);
            u64 acc[5];
#pragma unroll
            for (int r = 0; r < 5; ++r)
                acc[r] = ffma2(xt2, wihP[r], biasP[r]);

#pragma unroll
            for (int k = 0; k < 10; ++k) {
                u64 p = pack2(hj[2 * k], hj[2 * k + 1]);
#pragma unroll
                for (int r = 0; r < 5; ++r)
                    acc[r] = ffma2(p, wJ[r][k], acc[r]);
            }
#pragma unroll
            for (int r = 0; r < 5; ++r) {
                float lo, hi;
                unpack2(acc[r], lo, hi);
                h[r] = fmaxf(lo + hi, 0.0f);
            }
        }
        xv = xnext;
    }

    // Scalar tail (not taken for T=1000).
    for (int t = nChunks << 2; t < T; ++t) {
        float xt = xb[t];
        float hj[HID];
#pragma unroll
        for (int j = 0; j < HID; ++j)
            hj[j] = __shfl_sync(0xffffffffu, h[j % 5], j / 5, QUAD);
        u64 xt2 = dup2(xt);
        u64 acc[5];
#pragma unroll
        for (int r = 0; r < 5; ++r)
            acc[r] = ffma2(xt2, wihP[r], biasP[r]);
#pragma unroll
        for (int k = 0; k < 10; ++k) {
            u64 p = pack2(hj[2 * k], hj[2 * k + 1]);
#pragma unroll
            for (int r = 0; r < 5; ++r)
                acc[r] = ffma2(p, wJ[r][k], acc[r]);
        }
#pragma unroll
        for (int r = 0; r < 5; ++r) {
            float lo, hi;
            unpack2(acc[r], lo, hi);
            h[r] = fmaxf(lo + hi, 0.0f);
        }
    }

    // Head: out[b] = h . fc_w + fc_b ; quad butterfly reduction.
    float p = 0.0f;
#pragma unroll
    for (int r = 0; r < 5; ++r) p = fmaf(h[r], fcw[r0 + r], p);
    p += __shfl_xor_sync(0xffffffffu, p, 1, QUAD);
    p += __shfl_xor_sync(0xffffffffu, p, 2, QUAD);
    if (q == 0) out[batch] = p + fcb[0];
}

extern "C" void kernel_launch(void* const* d_in, const int* in_sizes, int n_in,
                              void* d_out, int out_size)
{
    const float* x    = (const float*)d_in[0];
    const float* Wih  = (const float*)d_in[1];
    const float* Whh  = (const float*)d_in[2];
    const float* bih  = (const float*)d_in[3];
    const float* bhh  = (const float*)d_in[4];
    const float* fcw  = (const float*)d_in[5];
    const float* fcb  = (const float*)d_in[6];
    float* out = (float*)d_out;

    int B = out_size;
    int T = in_sizes[0] / B;

    const int threads = 64;               // 16 batches/CTA -> 256 CTAs at B=4096
    int total = B * QUAD;
    int blocks = (total + threads - 1) / threads;
    rnn_fused_kernel<<<blocks, threads>>>(x, Wih, Whh, bih, bhh, fcw, fcb, out, B, T);
}